// round 6
// baseline (speedup 1.0000x reference)
#include <cuda_runtime.h>
#include <math.h>

typedef unsigned int u32; typedef unsigned long long u64;

#define BB 8
#define NSEQ 4096
#define DDIM 512
#define ESCALE 0.2102241038134287f

// ---------------- scratch ----------------
__device__ __align__(1024) float g_WTq[DDIM*DDIM], g_WTk[DDIM*DDIM], g_WTv[DDIM*DDIM];
__device__ __align__(1024) float g_Xr[3][BB*NSEQ*DDIM]; // tf32-rounded x_q/x_k/x_v
__device__ __align__(1024) float g_Qe [BB*NSEQ*DDIM];   // exp(Q/s), tf32-rounded
__device__ __align__(1024) float g_KT [BB*DDIM*NSEQ];   // exp(K/s)^T
__device__ __align__(1024) float g_VT [BB*DDIM*NSEQ];   // V^T
__device__ __align__(1024) float g_BmT[BB*DDIM*DDIM];   // (scaled Bm)^T
__device__ float g_pQ[BB*16*DDIM], g_Lk[BB*DDIM], g_nrm[BB*DDIM];

// ---------------- helpers ----------------
__device__ __forceinline__ u32 s2u(const void* p) {
    u32 a;
    asm("{ .reg .u64 t; cvta.to.shared.u64 t, %1; cvt.u32.u64 %0, t; }" : "=r"(a) : "l"(p));
    return a;
}
__device__ __forceinline__ u32 tf32r(float f) {
    u32 r; asm("cvt.rna.tf32.f32 %0, %1;" : "=r"(r) : "f"(f)); return r;
}
__device__ __forceinline__ float tf32rf(float f) { return __uint_as_float(tf32r(f)); }
__device__ __forceinline__ void cp16(u32 smem, const void* g) {
    asm volatile("cp.async.cg.shared.global [%0], [%1], 16;" :: "r"(smem), "l"(g));
}
__device__ __forceinline__ void cpcommit() { asm volatile("cp.async.commit_group;" ::: "memory"); }
__device__ __forceinline__ void cpwait1() { asm volatile("cp.async.wait_group 1;" ::: "memory"); }
__device__ __forceinline__ void cpwait0() { asm volatile("cp.async.wait_group 0;" ::: "memory"); }

#define MMA(ac, a, b0, b1)                                                        \
    asm volatile("mma.sync.aligned.m16n8k8.row.col.f32.tf32.tf32.f32 "            \
        "{%0,%1,%2,%3}, {%4,%5,%6,%7}, {%8,%9}, {%0,%1,%2,%3};"                   \
        : "+f"((ac)[0]), "+f"((ac)[1]), "+f"((ac)[2]), "+f"((ac)[3])              \
        : "r"((a)[0]), "r"((a)[1]), "r"((a)[2]), "r"((a)[3]), "r"(b0), "r"(b1))

#define LDSM4(rr, addr)                                                           \
    asm volatile("ldmatrix.sync.aligned.m8n8.x4.shared.b16 {%0,%1,%2,%3}, [%4];"  \
        : "=r"((rr)[0]), "=r"((rr)[1]), "=r"((rr)[2]), "=r"((rr)[3]) : "r"(addr))

// ---------------------------------------------------------------------------
// TF32 mma.sync GEMM: C[128 x 128] tile, K-chunk 32, 8 warps (2m x 4n),
// warp tile 64 x 32, ldmatrix fragment loads, 3-stage cp.async pipeline.
// A: [m][k] row-major (lda), B: [n][k] row-major (ldb)  -> C = A * B^T.
// All operands pre-rounded to tf32.
// EPI: 0 Q (bias+exp, row out) 1 K (bias+exp, transposed) 2 V (bias, transposed)
//      3 Bm (nrm row scale, transposed) 4 Z (plain fp32, row out)
// ---------------------------------------------------------------------------
template <int EPI>
__global__ void __launch_bounds__(256, 1)
gmma(const float* __restrict__ A, const float* __restrict__ Bmat,
     const float* __restrict__ aux, float* __restrict__ outp,
     long sA, long sB, long sO, int lda, int ldb, int ldo, int K)
{
    extern __shared__ float sm[];
    const int tid = threadIdx.x;
    const int w = tid >> 5, lane = tid & 31;
    const int r = lane >> 2, cq = lane & 3;
    const int b = blockIdx.z, m0 = blockIdx.y * 128, n0 = blockIdx.x * 128;
    const int mw = (w & 1) * 64, nw = (w >> 1) * 32;

    const float* pA = A    + (size_t)b * sA + (size_t)m0 * lda;
    const float* pB = Bmat + (size_t)b * sB + (size_t)n0 * ldb;

    float acc[4][4][4];
    #pragma unroll
    for (int mf = 0; mf < 4; mf++)
        #pragma unroll
        for (int nf = 0; nf < 4; nf++)
            #pragma unroll
            for (int e = 0; e < 4; e++) acc[mf][nf][e] = 0.f;

    const u32 smu = s2u(sm);
    // ldmatrix per-lane offsets (in floats)
    const int A_lo = (lane & 15) * 36 + (lane >> 4) * 4;
    const int B_lo = ((lane & 7) + ((lane & 16) ? 8 : 0)) * 36 + ((lane & 8) ? 4 : 0);

    // per stage: A tile [128][36] + B tile [128][36] = 9216 floats
    auto loadchunk = [&](int c, int s) {
        float* dA = sm + s * 9216;
        float* dB = dA + 4608;
        #pragma unroll
        for (int j = 0; j < 4; j++) {
            int e = tid + j * 256, m = e >> 3, kq = e & 7;
            cp16(s2u(dA + m * 36 + kq * 4), pA + (size_t)m * lda + c * 32 + kq * 4);
        }
        #pragma unroll
        for (int j = 0; j < 4; j++) {
            int e = tid + j * 256, m = e >> 3, kq = e & 7;
            cp16(s2u(dB + m * 36 + kq * 4), pB + (size_t)m * ldb + c * 32 + kq * 4);
        }
        cpcommit();
    };

    auto compute = [&](int s) {
        const u32 As_u = smu + s * 36864;
        const u32 Bs_u = As_u + 18432;
        #pragma unroll
        for (int ks = 0; ks < 4; ks++) {
            const int kk = ks * 8;
            u32 a[4][4], bf[2][4];
            #pragma unroll
            for (int mf = 0; mf < 4; mf++)
                LDSM4(a[mf], As_u + 4u * (u32)((mw + mf * 16) * 36 + kk + A_lo));
            #pragma unroll
            for (int p = 0; p < 2; p++)
                LDSM4(bf[p], Bs_u + 4u * (u32)((nw + p * 16) * 36 + kk + B_lo));
            #pragma unroll
            for (int mf = 0; mf < 4; mf++) {
                #pragma unroll
                for (int nf = 0; nf < 4; nf++) {
                    MMA(acc[mf][nf], a[mf], bf[nf >> 1][(nf & 1) * 2],
                        bf[nf >> 1][(nf & 1) * 2 + 1]);
                }
            }
        }
    };

    const int C = K >> 5;
    loadchunk(0, 0);
    if (C > 1) loadchunk(1, 1);
    for (int c = 0; c < C; c++) {
        if (c + 1 < C) cpwait1(); else cpwait0();
        __syncthreads();
        if (c + 2 < C) loadchunk(c + 2, (c + 2) % 3);
        compute(c % 3);
    }
    __syncthreads();

    // ---------------- epilogue ----------------
    float* sf = sm;   // 128 x (pitch 132)
    #pragma unroll
    for (int mf = 0; mf < 4; mf++) {
        #pragma unroll
        for (int nf = 0; nf < 4; nf++) {
            const int mr = mw + mf * 16 + r;
            const int nc = nw + nf * 8 + 2 * cq;
            float v0 = acc[mf][nf][0], v1 = acc[mf][nf][1];
            float v2 = acc[mf][nf][2], v3 = acc[mf][nf][3];
            if constexpr (EPI == 0 || EPI == 1) {
                const float bz0 = aux[n0 + nc], bz1 = aux[n0 + nc + 1];
                v0 = tf32rf(expf((v0 + bz0) * ESCALE));
                v1 = tf32rf(expf((v1 + bz1) * ESCALE));
                v2 = tf32rf(expf((v2 + bz0) * ESCALE));
                v3 = tf32rf(expf((v3 + bz1) * ESCALE));
            } else if constexpr (EPI == 2) {
                const float bz0 = aux[n0 + nc], bz1 = aux[n0 + nc + 1];
                v0 = tf32rf(v0 + bz0); v1 = tf32rf(v1 + bz1);
                v2 = tf32rf(v2 + bz0); v3 = tf32rf(v3 + bz1);
            } else if constexpr (EPI == 3) {
                const float s0 = aux[b * DDIM + m0 + mr];
                const float s8 = aux[b * DDIM + m0 + mr + 8];
                v0 = tf32rf(v0 * s0); v1 = tf32rf(v1 * s0);
                v2 = tf32rf(v2 * s8); v3 = tf32rf(v3 * s8);
            }
            if constexpr (EPI == 0 || EPI == 4) {
                sf[mr * 132 + nc]           = v0;
                sf[mr * 132 + nc + 1]       = v1;
                sf[(mr + 8) * 132 + nc]     = v2;
                sf[(mr + 8) * 132 + nc + 1] = v3;
            } else {
                sf[nc * 132 + mr]           = v0;
                sf[(nc + 1) * 132 + mr]     = v1;
                sf[nc * 132 + mr + 8]       = v2;
                sf[(nc + 1) * 132 + mr + 8] = v3;
            }
        }
    }
    __syncthreads();

    float* po = outp + (size_t)b * sO;
    if constexpr (EPI == 0 || EPI == 4) {
        for (int i = tid; i < 128 * 32; i += 256) {
            int rr = i >> 5, sg = i & 31;
            float4 vv = *(float4*)&sf[rr * 132 + sg * 4];
            *(float4*)(po + (size_t)(m0 + rr) * ldo + n0 + sg * 4) = vv;
        }
    } else {
        for (int i = tid; i < 128 * 32; i += 256) {
            int cc = i >> 5, sg = i & 31;
            float4 vv = *(float4*)&sf[cc * 132 + sg * 4];
            *(float4*)(po + (size_t)(n0 + cc) * ldo + m0 + sg * 4) = vv;
        }
    }
}

// ---------------- small kernels ----------------
__global__ void round4(const float4* __restrict__ in, float4* __restrict__ out)
{
    size_t i = (size_t)blockIdx.x * 256 + threadIdx.x;   // grid covers exactly n/4
    float4 v = in[i];
    v.x = tf32rf(v.x); v.y = tf32rf(v.y); v.z = tf32rf(v.z); v.w = tf32rf(v.w);
    out[i] = v;
}

__global__ void conv_Wt(const float* __restrict__ W, float* __restrict__ WT)
{
    int i = blockIdx.x * 256 + threadIdx.x;
    int n = i & 511, k = i >> 9;
    WT[(size_t)n * DDIM + k] = tf32rf(W[(size_t)k * DDIM + n]);
}

__global__ void colsumQ(const float* __restrict__ Q, float* __restrict__ part)
{
    const int d = blockIdx.x * 256 + threadIdx.x;
    const int ch = blockIdx.y, b = blockIdx.z;
    const float* p = Q + ((size_t)b * NSEQ + (size_t)ch * 256) * DDIM + d;
    float s0 = 0.f, s1 = 0.f, s2 = 0.f, s3 = 0.f;
    for (int n = 0; n < 256; n += 4) {
        s0 += p[(size_t)(n + 0) * DDIM];
        s1 += p[(size_t)(n + 1) * DDIM];
        s2 += p[(size_t)(n + 2) * DDIM];
        s3 += p[(size_t)(n + 3) * DDIM];
    }
    part[((size_t)b * 16 + ch) * DDIM + d] = (s0 + s1) + (s2 + s3);
}

__global__ void colsumK(const float* __restrict__ KT, float* __restrict__ Lk)
{
    __shared__ float red[128];
    const int d = blockIdx.x, b = blockIdx.y, t = threadIdx.x;
    const float4* p = (const float4*)(KT + ((size_t)b * DDIM + d) * NSEQ);
    float s = 0.f;
    for (int i = t; i < NSEQ / 4; i += 128) {
        float4 v = p[i];
        s += (v.x + v.y) + (v.z + v.w);
    }
    red[t] = s;
    __syncthreads();
    for (int st = 64; st > 0; st >>= 1) {
        if (t < st) red[t] += red[t + st];
        __syncthreads();
    }
    if (t == 0) Lk[(size_t)b * DDIM + d] = red[0];
}

__global__ void combine_nrm(const float* __restrict__ part, const float* __restrict__ Lk,
                            float* __restrict__ nrm)
{
    const int d = blockIdx.x * 256 + threadIdx.x;
    const int b = blockIdx.y;
    float lq = 0.f;
    #pragma unroll
    for (int c = 0; c < 16; c++) lq += part[((size_t)b * 16 + c) * DDIM + d];
    nrm[(size_t)b * DDIM + d] = 1.0f / (lq * Lk[(size_t)b * DDIM + d]);
}

// ---------------- launch ----------------
extern "C" void kernel_launch(void* const* d_in, const int* in_sizes, int n_in,
                              void* d_out, int out_size)
{
    const float* x_q = (const float*)d_in[0];
    const float* x_k = (const float*)d_in[1];
    const float* x_v = (const float*)d_in[2];
    const float* W_q = (const float*)d_in[3];
    const float* b_q = (const float*)d_in[4];
    const float* W_k = (const float*)d_in[5];
    const float* b_k = (const float*)d_in[6];
    const float* W_v = (const float*)d_in[7];
    const float* b_v = (const float*)d_in[8];
    float* out = (float*)d_out;

    float *WTq, *WTk, *WTv, *Xr, *Qe, *KT, *VT, *BmT, *pQ, *Lk, *nrm;
    cudaGetSymbolAddress((void**)&WTq, g_WTq);
    cudaGetSymbolAddress((void**)&WTk, g_WTk);
    cudaGetSymbolAddress((void**)&WTv, g_WTv);
    cudaGetSymbolAddress((void**)&Xr,  g_Xr);
    cudaGetSymbolAddress((void**)&Qe,  g_Qe);
    cudaGetSymbolAddress((void**)&KT,  g_KT);
    cudaGetSymbolAddress((void**)&VT,  g_VT);
    cudaGetSymbolAddress((void**)&BmT, g_BmT);
    cudaGetSymbolAddress((void**)&pQ,  g_pQ);
    cudaGetSymbolAddress((void**)&Lk,  g_Lk);
    cudaGetSymbolAddress((void**)&nrm, g_nrm);

    const long sX  = (long)NSEQ * DDIM;
    const long sT  = (long)DDIM * NSEQ;
    const long sBm = (long)DDIM * DDIM;
    float* xqr = Xr;
    float* xkr = Xr + sX * BB;
    float* xvr = Xr + 2 * sX * BB;

    const int SM = 110592;   // 3 stages x 9216 floats
    cudaFuncSetAttribute(gmma<0>, cudaFuncAttributeMaxDynamicSharedMemorySize, SM);
    cudaFuncSetAttribute(gmma<1>, cudaFuncAttributeMaxDynamicSharedMemorySize, SM);
    cudaFuncSetAttribute(gmma<2>, cudaFuncAttributeMaxDynamicSharedMemorySize, SM);
    cudaFuncSetAttribute(gmma<3>, cudaFuncAttributeMaxDynamicSharedMemorySize, SM);
    cudaFuncSetAttribute(gmma<4>, cudaFuncAttributeMaxDynamicSharedMemorySize, SM);

    // Pre-round activations + weights (weights also transposed) to tf32.
    const int NR = (int)(sX * BB / 4);
    round4<<<NR / 256, 256>>>((const float4*)x_q, (float4*)xqr);
    round4<<<NR / 256, 256>>>((const float4*)x_k, (float4*)xkr);
    round4<<<NR / 256, 256>>>((const float4*)x_v, (float4*)xvr);
    conv_Wt<<<1024, 256>>>(W_q, WTq);
    conv_Wt<<<1024, 256>>>(W_k, WTk);
    conv_Wt<<<1024, 256>>>(W_v, WTv);

    dim3 gp(4, 32, 8);
    gmma<0><<<gp, 256, SM>>>(xqr, WTq, b_q, Qe, sX, 0, sX, DDIM, DDIM, DDIM, DDIM);
    gmma<1><<<gp, 256, SM>>>(xkr, WTk, b_k, KT, sX, 0, sT, DDIM, DDIM, NSEQ, DDIM);
    gmma<2><<<gp, 256, SM>>>(xvr, WTv, b_v, VT, sX, 0, sT, DDIM, DDIM, NSEQ, DDIM);

    colsumQ<<<dim3(2, 16, 8), 256>>>(Qe, pQ);
    colsumK<<<dim3(512, 8), 128>>>(KT, Lk);
    combine_nrm<<<dim3(2, 8), 256>>>(pQ, Lk, nrm);

    // Bm^T = ((KT * VT^T) scaled by nrm rows)^T
    dim3 gb(4, 4, 8);
    gmma<3><<<gb, 256, SM>>>(KT, VT, nrm, BmT, sT, sT, sBm, NSEQ, NSEQ, DDIM, NSEQ);

    // Z = Qe * BmT^T
    dim3 gz(4, 32, 8);
    gmma<4><<<gz, 256, SM>>>(Qe, BmT, nullptr, out, sX, sBm, sX, DDIM, DDIM, DDIM, DDIM);
}